// round 1
// baseline (speedup 1.0000x reference)
#include <cuda_runtime.h>
#include <cuda_bf16.h>

// Problem constants (fixed shapes for this dataset)
// B=4, N=1024, C=16, H=W=128
#define BB 4
#define NN 1024
#define CC 16
#define HW 128

// Scratch: ev transposed [b][gv][n], eu [b][n][gu] (+padding for prefetch overrun)
__device__ float g_ev[BB * HW * NN];
__device__ float g_eu[BB * NN * HW + 2048];

__device__ __forceinline__ float ex2f(float x) {
    float y;
    asm("ex2.approx.ftz.f32 %0, %1;" : "=f"(y) : "f"(x));
    return y;
}

// ---------------------------------------------------------------------------
// Kernel A: project points, compute separable Gaussian factors.
// grid = B*N/32 = 128 blocks, 128 threads. Block handles 32 points of one batch.
// ---------------------------------------------------------------------------
__global__ void __launch_bounds__(128) proj_kernel(
    const float* __restrict__ Kc,
    const float* __restrict__ RT,
    const float* __restrict__ pts3d,
    const float* __restrict__ scale)
{
    const int b  = blockIdx.x >> 5;
    const int n0 = (blockIdx.x & 31) << 5;
    const int tid = threadIdx.x;

    __shared__ float su[32], sv[32], sinv[32], smask[32];

    if (tid < 32) {
        const int n = n0 + tid;
        const float* rt = RT + b * 12;
        const float* p  = pts3d + (b * NN + n) * 3;
        float p0 = p[0], p1 = p[1], p2 = p[2];
        float l0 = rt[0] * p0 + rt[1] * p1 + rt[2]  * p2 + rt[3];
        float l1 = rt[4] * p0 + rt[5] * p1 + rt[6]  * p2 + rt[7];
        float l2 = rt[8] * p0 + rt[9] * p1 + rt[10] * p2 + rt[11];
        float x = Kc[0] * l0 + Kc[1] * l1 + Kc[2] * l2;
        float y = Kc[3] * l0 + Kc[4] * l1 + Kc[5] * l2;
        float z = Kc[6] * l0 + Kc[7] * l1 + Kc[8] * l2;
        float mask = (z > 0.1f) ? 1.0f : 0.0f;
        float zc = fmaxf(z, 0.1f);
        float sig = Kc[0] * 0.03125f;          // sigma = K[0,0]/32 (N != 1)
        float inv = 1.0f / (scale[b * NN + n] * sig * sig);
        su[tid]   = x / zc;
        sv[tid]   = y / zc;
        sinv[tid] = -1.4426950408889634f * inv; // fold -log2(e)
        smask[tid] = mask;
    }
    __syncthreads();

    const int warp = tid >> 5;
    const int lane = tid & 31;

    // ev[b][gv][n0+lane]: thread owns point `lane`, warp covers 32 gv rows.
    {
        const float v  = sv[lane];
        const float ni = sinv[lane];
        float* dst = g_ev + (b * HW) * NN + n0 + lane;
        #pragma unroll 8
        for (int j = 0; j < 32; j++) {
            const int gv = warp * 32 + j;
            float d = v - (float)gv;
            dst[gv * NN] = ex2f(d * d * ni);
        }
    }
    // eu[b][n0+i][gu]: thread owns column gu = tid, loops points (mask folded here).
    {
        const float fgu = (float)tid;
        float* dst = g_eu + (b * NN + n0) * HW + tid;
        #pragma unroll 8
        for (int i = 0; i < 32; i++) {
            float d = su[i] - fgu;
            dst[i * HW] = ex2f(d * d * sinv[i]) * smask[i];
        }
    }
}

// ---------------------------------------------------------------------------
// Kernel B: img[b,c,gv,gu] = sum_n feat[b,n,c] * ev[b,n,gv] * eu[b,n,gu]
// grid = B * 32 = 128 blocks (single wave); block = (b, 4 gv rows);
// thread = one gu column; 4 rows x 16 channels fp32 accumulators,
// packed as f32x2 pairs along c so feat pairs load via LDS.64.
// ---------------------------------------------------------------------------
__global__ void __launch_bounds__(128, 1) accum_kernel(
    const float* __restrict__ feat,
    float* __restrict__ out)
{
    const int b   = blockIdx.x >> 5;
    const int gv0 = (blockIdx.x & 31) << 2;   // 4 rows per block
    const int gu  = threadIdx.x;

    __shared__ float sfeat[128][16];                 // chunk of feat [n][c]
    __shared__ unsigned long long sev2[4][128];      // (ev,ev) packed per row

    const float* evb   = g_ev + (b * HW + gv0) * NN;
    const float* eub   = g_eu + b * NN * HW + gu;
    const float* featb = feat + b * NN * CC;

    unsigned long long acc[4][8];
    #pragma unroll
    for (int r = 0; r < 4; r++)
        #pragma unroll
        for (int c = 0; c < 8; c++) acc[r][c] = 0ULL;

    float eu_cur[8], eu_nxt[8];
    #pragma unroll
    for (int u = 0; u < 8; u++) eu_cur[u] = eub[u * HW];

    for (int chunk = 0; chunk < 8; chunk++) {
        const int n0 = chunk * 128;
        __syncthreads();
        {
            // stage feat chunk: thread loads its own n-row (coalesced float4)
            float4* d4 = reinterpret_cast<float4*>(&sfeat[threadIdx.x][0]);
            const float4* s4 =
                reinterpret_cast<const float4*>(featb + (n0 + threadIdx.x) * CC);
            d4[0] = s4[0]; d4[1] = s4[1]; d4[2] = s4[2]; d4[3] = s4[3];
            // stage ev rows, pre-duplicated into f32x2
            #pragma unroll
            for (int r = 0; r < 4; r++) {
                float e = evb[r * NN + n0 + threadIdx.x];
                unsigned long long ep;
                asm("mov.b64 %0, {%1, %1};" : "=l"(ep) : "f"(e));
                sev2[r][threadIdx.x] = ep;
            }
        }
        __syncthreads();

        #pragma unroll 1
        for (int j = 0; j < 128; j += 8) {
            // prefetch next 8 eu values (padding absorbs the final overrun)
            const float* pf = eub + (n0 + j + 8) * HW;
            #pragma unroll
            for (int u = 0; u < 8; u++) eu_nxt[u] = pf[u * HW];

            #pragma unroll
            for (int u = 0; u < 8; u++) {
                const int n = j + u;
                unsigned long long eup;
                asm("mov.b64 %0, {%1, %1};" : "=l"(eup) : "f"(eu_cur[u]));
                unsigned long long f[8];
                const unsigned long long* fp =
                    reinterpret_cast<const unsigned long long*>(&sfeat[n][0]);
                #pragma unroll
                for (int c = 0; c < 8; c++) f[c] = fp[c];
                #pragma unroll
                for (int r = 0; r < 4; r++) {
                    unsigned long long wp;
                    asm("mul.rn.f32x2 %0, %1, %2;"
                        : "=l"(wp) : "l"(sev2[r][n]), "l"(eup));
                    #pragma unroll
                    for (int c = 0; c < 8; c++)
                        asm("fma.rn.f32x2 %0, %1, %2, %0;"
                            : "+l"(acc[r][c]) : "l"(f[c]), "l"(wp));
                }
            }
            #pragma unroll
            for (int u = 0; u < 8; u++) eu_cur[u] = eu_nxt[u];
        }
    }

    // write out[b][c][gv][gu]
    float* ob = out + (b * CC) * (HW * HW) + gv0 * HW + gu;
    #pragma unroll
    for (int r = 0; r < 4; r++) {
        #pragma unroll
        for (int c = 0; c < 8; c++) {
            float lo, hi;
            asm("mov.b64 {%0, %1}, %2;" : "=f"(lo), "=f"(hi) : "l"(acc[r][c]));
            ob[(2 * c)     * (HW * HW) + r * HW] = lo;
            ob[(2 * c + 1) * (HW * HW) + r * HW] = hi;
        }
    }
}

extern "C" void kernel_launch(void* const* d_in, const int* in_sizes, int n_in,
                              void* d_out, int out_size)
{
    const float* Kc    = (const float*)d_in[0];
    const float* RT    = (const float*)d_in[1];
    const float* pts3d = (const float*)d_in[2];
    const float* feat  = (const float*)d_in[3];
    const float* scale = (const float*)d_in[4];
    float* out = (float*)d_out;

    proj_kernel<<<BB * NN / 32, 128>>>(Kc, RT, pts3d, scale);
    accum_kernel<<<BB * 32, 128>>>(feat, out);
}

// round 2
// speedup vs baseline: 1.3635x; 1.3635x over previous
#include <cuda_runtime.h>
#include <cuda_bf16.h>

// Problem constants (fixed shapes for this dataset)
// B=4, N=1024, C=16, H=W=128
#define BB 4
#define NN 1024
#define CC 16
#define HW 128

// Scratch: ev transposed [b][gv][n], eu [b][n][gu] (+padding for prefetch overrun)
__device__ float g_ev[BB * HW * NN];
__device__ float g_eu[BB * NN * HW + 2048];

__device__ __forceinline__ float ex2f(float x) {
    float y;
    asm("ex2.approx.ftz.f32 %0, %1;" : "=f"(y) : "f"(x));
    return y;
}

// ---------------------------------------------------------------------------
// Kernel A: project points, compute separable Gaussian factors.
// grid = B*N/32 = 128 blocks, 128 threads. Block handles 32 points of one batch.
// ---------------------------------------------------------------------------
__global__ void __launch_bounds__(128) proj_kernel(
    const float* __restrict__ Kc,
    const float* __restrict__ RT,
    const float* __restrict__ pts3d,
    const float* __restrict__ scale)
{
    const int b  = blockIdx.x >> 5;
    const int n0 = (blockIdx.x & 31) << 5;
    const int tid = threadIdx.x;

    __shared__ float su[32], sv[32], sinv[32], smask[32];

    if (tid < 32) {
        const int n = n0 + tid;
        const float* rt = RT + b * 12;
        const float* p  = pts3d + (b * NN + n) * 3;
        float p0 = p[0], p1 = p[1], p2 = p[2];
        float l0 = rt[0] * p0 + rt[1] * p1 + rt[2]  * p2 + rt[3];
        float l1 = rt[4] * p0 + rt[5] * p1 + rt[6]  * p2 + rt[7];
        float l2 = rt[8] * p0 + rt[9] * p1 + rt[10] * p2 + rt[11];
        float x = Kc[0] * l0 + Kc[1] * l1 + Kc[2] * l2;
        float y = Kc[3] * l0 + Kc[4] * l1 + Kc[5] * l2;
        float z = Kc[6] * l0 + Kc[7] * l1 + Kc[8] * l2;
        float mask = (z > 0.1f) ? 1.0f : 0.0f;
        float zc = fmaxf(z, 0.1f);
        float sig = Kc[0] * 0.03125f;          // sigma = K[0,0]/32 (N != 1)
        float inv = 1.0f / (scale[b * NN + n] * sig * sig);
        su[tid]   = x / zc;
        sv[tid]   = y / zc;
        sinv[tid] = -1.4426950408889634f * inv; // fold -log2(e)
        smask[tid] = mask;
    }
    __syncthreads();

    const int warp = tid >> 5;
    const int lane = tid & 31;

    // ev[b][gv][n0+lane]: thread owns point `lane`, warp covers 32 gv rows.
    {
        const float v  = sv[lane];
        const float ni = sinv[lane];
        float* dst = g_ev + (b * HW) * NN + n0 + lane;
        #pragma unroll 8
        for (int j = 0; j < 32; j++) {
            const int gv = warp * 32 + j;
            float d = v - (float)gv;
            dst[gv * NN] = ex2f(d * d * ni);
        }
    }
    // eu[b][n0+i][gu]: thread owns column gu = tid, loops points (mask folded here).
    {
        const float fgu = (float)tid;
        float* dst = g_eu + (b * NN + n0) * HW + tid;
        #pragma unroll 8
        for (int i = 0; i < 32; i++) {
            float d = su[i] - fgu;
            dst[i * HW] = ex2f(d * d * sinv[i]) * smask[i];
        }
    }
}

// ---------------------------------------------------------------------------
// Kernel B: img[b,c,gv,gu] = sum_n feat[b,n,c] * ev[b,n,gv] * eu[b,n,gu]
// grid = B * 32 = 128 blocks; block = (b, 4 gv rows); 512 threads:
//   tid = gu + 128*csel + 256*nsel
//   gu   : pixel column (128)
//   csel : channel half (ch 0-7 vs 8-15)    -> acc = 4 rows x 4 c-pairs
//   nsel : n half (n in [0,512) vs [512,1024)) -> combined via smem reduce
// 16 warps/SM (occ 25%), 4 warps/SMSP to saturate the FMA pipe.
// ---------------------------------------------------------------------------
__global__ void __launch_bounds__(512, 1) accum_kernel(
    const float* __restrict__ feat,
    float* __restrict__ out)
{
    const int b   = blockIdx.x >> 5;
    const int gv0 = (blockIdx.x & 31) << 2;   // 4 rows per block
    const int tid  = threadIdx.x;
    const int gu   = tid & 127;
    const int csel = (tid >> 7) & 1;
    const int nsel = tid >> 8;

    __shared__ float sfeat[2][128][16];              // per n-group feat chunk
    __shared__ unsigned long long sev2[2][4][128];   // per n-group (ev,ev) pairs

    const float* evb   = g_ev + (b * HW + gv0) * NN;
    const float* eub   = g_eu + b * NN * HW + gu;
    const float* featb = feat + b * NN * CC;

    unsigned long long acc[4][4];
    #pragma unroll
    for (int r = 0; r < 4; r++)
        #pragma unroll
        for (int c = 0; c < 4; c++) acc[r][c] = 0ULL;

    const int nbase = nsel << 9;  // 0 or 512

    float eu_cur[8], eu_nxt[8];
    #pragma unroll
    for (int u = 0; u < 8; u++) eu_cur[u] = eub[(nbase + u) * HW];

    for (int chunk = 0; chunk < 4; chunk++) {
        __syncthreads();
        // ---- stage this chunk for both n-groups (512 threads cooperate) ----
        {
            const int t = tid & 127;
            const int role = tid >> 7;             // 0,1: feat g0/g1  2,3: ev g0/g1
            if (role < 2) {
                const int n = (role << 9) + chunk * 128 + t;
                float4* d4 = reinterpret_cast<float4*>(&sfeat[role][t][0]);
                const float4* s4 = reinterpret_cast<const float4*>(featb + n * CC);
                d4[0] = s4[0]; d4[1] = s4[1]; d4[2] = s4[2]; d4[3] = s4[3];
            } else {
                const int g = role - 2;
                const int n = (g << 9) + chunk * 128 + t;
                #pragma unroll
                for (int r = 0; r < 4; r++) {
                    float e = evb[r * NN + n];
                    unsigned long long ep;
                    asm("mov.b64 %0, {%1, %1};" : "=l"(ep) : "f"(e));
                    sev2[g][r][t] = ep;
                }
            }
        }
        __syncthreads();

        #pragma unroll 1
        for (int j = 0; j < 128; j += 8) {
            // prefetch next 8 eu values (g_eu padding absorbs final overrun)
            const float* pf = eub + (nbase + chunk * 128 + j + 8) * HW;
            #pragma unroll
            for (int u = 0; u < 8; u++) eu_nxt[u] = pf[u * HW];

            #pragma unroll
            for (int u = 0; u < 8; u++) {
                const int n = j + u;
                unsigned long long eup;
                asm("mov.b64 %0, {%1, %1};" : "=l"(eup) : "f"(eu_cur[u]));
                unsigned long long f[4];
                const unsigned long long* fp =
                    reinterpret_cast<const unsigned long long*>(&sfeat[nsel][n][csel << 3]);
                #pragma unroll
                for (int c = 0; c < 4; c++) f[c] = fp[c];
                #pragma unroll
                for (int r = 0; r < 4; r++) {
                    unsigned long long wp;
                    asm("mul.rn.f32x2 %0, %1, %2;"
                        : "=l"(wp) : "l"(sev2[nsel][r][n]), "l"(eup));
                    #pragma unroll
                    for (int c = 0; c < 4; c++)
                        asm("fma.rn.f32x2 %0, %1, %2, %0;"
                            : "+l"(acc[r][c]) : "l"(f[c]), "l"(wp));
                }
            }
            #pragma unroll
            for (int u = 0; u < 8; u++) eu_cur[u] = eu_nxt[u];
        }
    }

    // ---- combine the two n-halves via shared memory (2 passes of 2 rows) ----
    unsigned long long* sred = reinterpret_cast<unsigned long long*>(&sfeat[0][0][0]);
    const int s = (csel << 7) + gu;  // 0..255
    #pragma unroll
    for (int half = 0; half < 2; half++) {
        __syncthreads();
        if (nsel == 1) {
            #pragma unroll
            for (int r2 = 0; r2 < 2; r2++)
                #pragma unroll
                for (int c = 0; c < 4; c++)
                    sred[s * 8 + r2 * 4 + c] = acc[half * 2 + r2][c];
        }
        __syncthreads();
        if (nsel == 0) {
            #pragma unroll
            for (int r2 = 0; r2 < 2; r2++)
                #pragma unroll
                for (int c = 0; c < 4; c++)
                    asm("add.rn.f32x2 %0, %0, %1;"
                        : "+l"(acc[half * 2 + r2][c]) : "l"(sred[s * 8 + r2 * 4 + c]));
        }
    }

    // ---- write out[b][c][gv][gu] (nsel==0 threads only) ----
    if (nsel == 0) {
        float* ob = out + (b * CC + (csel << 3)) * (HW * HW) + gv0 * HW + gu;
        #pragma unroll
        for (int r = 0; r < 4; r++) {
            #pragma unroll
            for (int c = 0; c < 4; c++) {
                float lo, hi;
                asm("mov.b64 {%0, %1}, %2;" : "=f"(lo), "=f"(hi) : "l"(acc[r][c]));
                ob[(2 * c)     * (HW * HW) + r * HW] = lo;
                ob[(2 * c + 1) * (HW * HW) + r * HW] = hi;
            }
        }
    }
}

extern "C" void kernel_launch(void* const* d_in, const int* in_sizes, int n_in,
                              void* d_out, int out_size)
{
    const float* Kc    = (const float*)d_in[0];
    const float* RT    = (const float*)d_in[1];
    const float* pts3d = (const float*)d_in[2];
    const float* feat  = (const float*)d_in[3];
    const float* scale = (const float*)d_in[4];
    float* out = (float*)d_out;

    proj_kernel<<<BB * NN / 32, 128>>>(Kc, RT, pts3d, scale);
    accum_kernel<<<BB * 32, 512>>>(feat, out);
}